// round 1
// baseline (speedup 1.0000x reference)
#include <cuda_runtime.h>
#include <cstdint>
#include <cstddef>

#define BS 64
#define MU 64
#define KA 64
#define DD 128
#define HH 128

// Scratch (device globals: allocation-free per harness rules)
__device__ float g_msg_m[BS * MU * DD];          // 2 MB
__device__ float g_msgk_part[8][BS * KA * DD];   // 16 MB (deterministic partials, no atomics)
__device__ float g_zm[BS * MU * HH];             // 2 MB
__device__ float g_zk[BS * KA * HH];             // 2 MB

// ---------------------------------------------------------------------------
// K1: one pass over inputs. Block = (b, m-chunk of 8).
//   msg_m[b,m,:]  = sum_k x[b,m,k,:]            (exact, written directly)
//   msgk_part[c][b,k,:] = sum_{m in chunk c} x  (partials, summed in K2)
// Thread t owns d-column t -> smem column ownership, zero conflicts, no syncs.
// ---------------------------------------------------------------------------
__global__ void k1_reduce(const float* __restrict__ in) {
    int b = blockIdx.x >> 3;
    int chunk = blockIdx.x & 7;
    int t = threadIdx.x;  // 128 threads = d index
    __shared__ float sk[KA][DD];
#pragma unroll
    for (int k = 0; k < KA; k++) sk[k][t] = 0.f;

    const float* base = in + ((size_t)(b * MU + chunk * 8) * KA) * DD + t;
#pragma unroll 1
    for (int m = 0; m < 8; m++) {
        const float* pm = base + (size_t)m * KA * DD;
        float acc = 0.f;
#pragma unroll 8
        for (int k = 0; k < KA; k++) {
            float v = pm[(size_t)k * DD];
            acc += v;
            sk[k][t] += v;
        }
        g_msg_m[(b * MU + chunk * 8 + m) * DD + t] = acc;
    }
    float* dst = &g_msgk_part[chunk][(b * KA) * DD + t];
#pragma unroll 8
    for (int k = 0; k < KA; k++) dst[k * DD] = sk[k][t];
}

// ---------------------------------------------------------------------------
// K2: zm[b,m,h] = msg_m[b,m,:] . Wm[h,:] ; zk[b,k,h] = msg_k[b,k,:] . Wk[h,:]
// Block = (side, b): 64 rows x 128 h, fp32 (exact). 8x8 register tiles.
// Dynamic smem: Ws[128][129] + Ms[64][129]  (~99 KB)
// ---------------------------------------------------------------------------
__global__ void __launch_bounds__(128) k2_bias(const float* __restrict__ Wm,
                                               const float* __restrict__ Wk) {
    extern __shared__ float s2[];
    float* Ws = s2;               // [128][129]
    float* Ms = s2 + 128 * 129;   // [64][129]
    int side = blockIdx.x >> 6;   // 0: zm (m-side), 1: zk (k-side)
    int b = blockIdx.x & 63;
    int t = threadIdx.x;  // 128

    const float* W = side ? Wk : Wm;
#pragma unroll 4
    for (int i = 0; i < HH; i++) Ws[i * 129 + t] = W[i * DD + t];

    if (!side) {
#pragma unroll 4
        for (int r = 0; r < 64; r++) Ms[r * 129 + t] = g_msg_m[(b * 64 + r) * DD + t];
    } else {
#pragma unroll 2
        for (int r = 0; r < 64; r++) {
            float s = 0.f;
#pragma unroll
            for (int c = 0; c < 8; c++) s += g_msgk_part[c][(b * 64 + r) * DD + t];
            Ms[r * 129 + t] = s;
        }
    }
    __syncthreads();

    int rt = t >> 4;   // 0..7: rows rt*8 .. rt*8+7
    int ht = t & 15;   // h = ht + 16*j, j=0..7 (stride-16 avoids smem conflicts)
    float acc[8][8];
#pragma unroll
    for (int i = 0; i < 8; i++)
#pragma unroll
        for (int j = 0; j < 8; j++) acc[i][j] = 0.f;

    for (int dd = 0; dd < DD; dd++) {
        float xv[8], wv[8];
#pragma unroll
        for (int i = 0; i < 8; i++) xv[i] = Ms[(rt * 8 + i) * 129 + dd];
#pragma unroll
        for (int j = 0; j < 8; j++) wv[j] = Ws[(ht + 16 * j) * 129 + dd];
#pragma unroll
        for (int i = 0; i < 8; i++)
#pragma unroll
            for (int j = 0; j < 8; j++) acc[i][j] += xv[i] * wv[j];
    }

    float* outp = side ? g_zk : g_zm;
#pragma unroll
    for (int i = 0; i < 8; i++)
#pragma unroll
        for (int j = 0; j < 8; j++)
            outp[(b * 64 + rt * 8 + i) * HH + ht + 16 * j] = acc[i][j];
}

// ---------------------------------------------------------------------------
// K3: out[n,h] = x[n,:] @ Wself[h,:]^T + zm[b*64+m, h] + zk[b*64+k, h]
// n = ((b*64+m)*64+k), rows = 262144. tf32 mma.sync m16n8k8.
// Block: 128 rows x 64 cols (n-half). Full K=128 in smem (no k-pipeline).
// Dynamic smem: As[128][132] + Bs[64][132] u32 (~99 KB) -> 2 blocks/SM.
// Consecutive bids share a row-tile (A reuse via L2).
// ---------------------------------------------------------------------------
__global__ void __launch_bounds__(256) k3_main(const float* __restrict__ in,
                                               const float* __restrict__ Wself,
                                               float* __restrict__ out) {
    extern __shared__ uint32_t s3[];
    uint32_t* As = s3;                 // [128][132]
    uint32_t* Bsm = s3 + 128 * 132;    // [64][132]
    int bid = blockIdx.x;
    int row0 = (bid >> 1) * 128;
    int n0 = (bid & 1) * 64;
    int t = threadIdx.x;  // 256

    // Load A tile (128 x 128 fp32) -> tf32 (round-to-nearest) in smem, pad 132
    const float4* A4 = reinterpret_cast<const float4*>(in + (size_t)row0 * DD);
    for (int i = t; i < 128 * 32; i += 256) {
        int r = i >> 5, c4 = i & 31;
        float4 v = A4[r * 32 + c4];
        uint32_t u0, u1, u2, u3;
        asm("cvt.rna.tf32.f32 %0, %1;" : "=r"(u0) : "f"(v.x));
        asm("cvt.rna.tf32.f32 %0, %1;" : "=r"(u1) : "f"(v.y));
        asm("cvt.rna.tf32.f32 %0, %1;" : "=r"(u2) : "f"(v.z));
        asm("cvt.rna.tf32.f32 %0, %1;" : "=r"(u3) : "f"(v.w));
        uint32_t* p = &As[r * 132 + c4 * 4];
        p[0] = u0; p[1] = u1; p[2] = u2; p[3] = u3;
    }
    // Load B half-tile (64 x 128 rows of Wself)
    const float4* B4 = reinterpret_cast<const float4*>(Wself + (size_t)n0 * DD);
    for (int i = t; i < 64 * 32; i += 256) {
        int r = i >> 5, c4 = i & 31;
        float4 v = B4[r * 32 + c4];
        uint32_t u0, u1, u2, u3;
        asm("cvt.rna.tf32.f32 %0, %1;" : "=r"(u0) : "f"(v.x));
        asm("cvt.rna.tf32.f32 %0, %1;" : "=r"(u1) : "f"(v.y));
        asm("cvt.rna.tf32.f32 %0, %1;" : "=r"(u2) : "f"(v.z));
        asm("cvt.rna.tf32.f32 %0, %1;" : "=r"(u3) : "f"(v.w));
        uint32_t* p = &Bsm[r * 132 + c4 * 4];
        p[0] = u0; p[1] = u1; p[2] = u2; p[3] = u3;
    }
    __syncthreads();

    int lane = t & 31, wid = t >> 5;
    int wm = wid & 3;   // 4 warps over rows (32 each)
    int wn = wid >> 2;  // 2 warps over cols (32 each within the 64-half)
    int lr = lane >> 2, lc = lane & 3;

    float c[2][4][4];
#pragma unroll
    for (int mt = 0; mt < 2; mt++)
#pragma unroll
        for (int nt = 0; nt < 4; nt++)
#pragma unroll
            for (int q = 0; q < 4; q++) c[mt][nt][q] = 0.f;

#pragma unroll
    for (int kk = 0; kk < 16; kk++) {
        int k0 = kk * 8;
        uint32_t a[2][4], bf[4][2];
#pragma unroll
        for (int mt = 0; mt < 2; mt++) {
            int r = wm * 32 + mt * 16 + lr;
            a[mt][0] = As[r * 132 + k0 + lc];
            a[mt][1] = As[(r + 8) * 132 + k0 + lc];
            a[mt][2] = As[r * 132 + k0 + 4 + lc];
            a[mt][3] = As[(r + 8) * 132 + k0 + 4 + lc];
        }
#pragma unroll
        for (int nt = 0; nt < 4; nt++) {
            int n = wn * 32 + nt * 8 + lr;
            bf[nt][0] = Bsm[n * 132 + k0 + lc];
            bf[nt][1] = Bsm[n * 132 + k0 + 4 + lc];
        }
#pragma unroll
        for (int mt = 0; mt < 2; mt++)
#pragma unroll
            for (int nt = 0; nt < 4; nt++)
                asm volatile(
                    "mma.sync.aligned.m16n8k8.row.col.f32.tf32.tf32.f32 "
                    "{%0,%1,%2,%3},{%4,%5,%6,%7},{%8,%9},{%0,%1,%2,%3};"
                    : "+f"(c[mt][nt][0]), "+f"(c[mt][nt][1]),
                      "+f"(c[mt][nt][2]), "+f"(c[mt][nt][3])
                    : "r"(a[mt][0]), "r"(a[mt][1]), "r"(a[mt][2]), "r"(a[mt][3]),
                      "r"(bf[nt][0]), "r"(bf[nt][1]));
    }

    // Epilogue: add zm (per b*64+m) and zk (per b*64+k), float2 stores
#pragma unroll
    for (int mt = 0; mt < 2; mt++) {
#pragma unroll
        for (int half = 0; half < 2; half++) {
            int rloc = wm * 32 + mt * 16 + lr + half * 8;
            int row_g = row0 + rloc;
            int bm = row_g >> 6;                                  // b*64 + m
            int bk = ((row_g >> 12) << 6) | (row_g & 63);         // b*64 + k
#pragma unroll
            for (int nt = 0; nt < 4; nt++) {
                int col = n0 + wn * 32 + nt * 8 + lc * 2;
                float2 zmv = *reinterpret_cast<const float2*>(&g_zm[bm * HH + col]);
                float2 zkv = *reinterpret_cast<const float2*>(&g_zk[bk * HH + col]);
                float2 o;
                o.x = c[mt][nt][half * 2 + 0] + zmv.x + zkv.x;
                o.y = c[mt][nt][half * 2 + 1] + zmv.y + zkv.y;
                *reinterpret_cast<float2*>(out + (size_t)row_g * HH + col) = o;
            }
        }
    }
}

extern "C" void kernel_launch(void* const* d_in, const int* in_sizes, int n_in,
                              void* d_out, int out_size) {
    const float* inputs = (const float*)d_in[0];
    const float* Wself  = (const float*)d_in[1];
    const float* Wm     = (const float*)d_in[2];
    const float* Wk     = (const float*)d_in[3];
    float* out = (float*)d_out;
    (void)in_sizes; (void)n_in; (void)out_size;

    const size_t S2 = (size_t)(128 * 129 + 64 * 129) * sizeof(float);     // ~99 KB
    const size_t S3 = (size_t)(128 * 132 + 64 * 132) * sizeof(uint32_t);  // ~99 KB
    cudaFuncSetAttribute(k2_bias, cudaFuncAttributeMaxDynamicSharedMemorySize, (int)S2);
    cudaFuncSetAttribute(k3_main, cudaFuncAttributeMaxDynamicSharedMemorySize, (int)S3);

    k1_reduce<<<512, 128>>>(inputs);
    k2_bias<<<128, 128, S2>>>(Wm, Wk);
    k3_main<<<4096, 256, S3>>>(inputs, Wself, out);
}

// round 3
// speedup vs baseline: 1.8068x; 1.8068x over previous
#include <cuda_runtime.h>
#include <cuda_bf16.h>
#include <cstdint>
#include <cstddef>

#define BS 64
#define MU 64
#define KA 64
#define DD 128
#define HH 128

#define ROWP 136                 // padded bf16 elems per smem row (272 B)
#define TILE_R 256               // rows per k3 tile
#define N_TILES 1024             // 262144 / 256
#define K3_THREADS 512

// Scratch (device globals: allocation-free per harness rules)
__device__ float g_msgm_part[4][BS * MU * DD];   // 8 MB
__device__ float g_msgk_part[8][BS * KA * DD];   // 16 MB
__device__ float g_zm[BS * MU * HH];             // 2 MB
__device__ float g_zk[BS * KA * HH];             // 2 MB

// ===========================================================================
// K1: grid = 64b x 8mc x 4kc = 2048 blocks, 128 threads (t = d index).
// All-register accumulation: 16 k-accs + 1 m-acc. No smem, no atomics.
// ===========================================================================
__global__ void __launch_bounds__(128) k1_reduce(const float* __restrict__ in) {
    int bid = blockIdx.x;
    int b = bid >> 5;
    int mc = (bid >> 2) & 7;
    int kc = bid & 3;
    int t = threadIdx.x;

    const float* base = in + ((size_t)((b * MU + mc * 8) * KA + kc * 16)) * DD + t;
    float ak[16];
#pragma unroll
    for (int k = 0; k < 16; k++) ak[k] = 0.f;

#pragma unroll 1
    for (int m = 0; m < 8; m++) {
        const float* pm = base + (size_t)m * KA * DD;
        float v[16];
#pragma unroll
        for (int k = 0; k < 16; k++) v[k] = pm[(size_t)k * DD];
        float am = 0.f;
#pragma unroll
        for (int k = 0; k < 16; k++) { am += v[k]; ak[k] += v[k]; }
        g_msgm_part[kc][(size_t)(b * MU + mc * 8 + m) * DD + t] = am;
    }
#pragma unroll
    for (int k = 0; k < 16; k++)
        g_msgk_part[mc][(size_t)(b * KA + kc * 16 + k) * DD + t] = ak[k];
}

// ===========================================================================
// K2: zm = msg_m @ Wm^T ; zk = msg_k @ Wk^T  (exact fp32, 8x8 reg tiles)
// Combines the k1 partials on the way in.
// ===========================================================================
__global__ void __launch_bounds__(128) k2_bias(const float* __restrict__ Wm,
                                               const float* __restrict__ Wk) {
    extern __shared__ float s2[];
    float* Ws = s2;               // [128][129]
    float* Ms = s2 + 128 * 129;   // [64][129]
    int side = blockIdx.x >> 6;
    int b = blockIdx.x & 63;
    int t = threadIdx.x;

    const float* W = side ? Wk : Wm;
#pragma unroll 4
    for (int i = 0; i < HH; i++) Ws[i * 129 + t] = W[i * DD + t];

    if (!side) {
#pragma unroll 2
        for (int r = 0; r < 64; r++) {
            float s = 0.f;
#pragma unroll
            for (int p = 0; p < 4; p++) s += g_msgm_part[p][(size_t)(b * 64 + r) * DD + t];
            Ms[r * 129 + t] = s;
        }
    } else {
#pragma unroll 2
        for (int r = 0; r < 64; r++) {
            float s = 0.f;
#pragma unroll
            for (int p = 0; p < 8; p++) s += g_msgk_part[p][(size_t)(b * 64 + r) * DD + t];
            Ms[r * 129 + t] = s;
        }
    }
    __syncthreads();

    int rt = t >> 4;
    int ht = t & 15;
    float acc[8][8];
#pragma unroll
    for (int i = 0; i < 8; i++)
#pragma unroll
        for (int j = 0; j < 8; j++) acc[i][j] = 0.f;

    for (int dd = 0; dd < DD; dd++) {
        float xv[8], wv[8];
#pragma unroll
        for (int i = 0; i < 8; i++) xv[i] = Ms[(rt * 8 + i) * 129 + dd];
#pragma unroll
        for (int j = 0; j < 8; j++) wv[j] = Ws[(ht + 16 * j) * 129 + dd];
#pragma unroll
        for (int i = 0; i < 8; i++)
#pragma unroll
            for (int j = 0; j < 8; j++) acc[i][j] += xv[i] * wv[j];
    }

    float* outp = side ? g_zk : g_zm;
#pragma unroll
    for (int i = 0; i < 8; i++)
#pragma unroll
        for (int j = 0; j < 8; j++)
            outp[(size_t)(b * 64 + rt * 8 + i) * HH + ht + 16 * j] = acc[i][j];
}

// ===========================================================================
// K3: persistent bf16 mma.sync m16n8k16 GEMM + fused bias epilogue.
// Grid 148 x 512 threads (16 warps). B (Wself) in smem once; A double-buffered
// 256-row tiles. Warp w owns rows [w*16, w*16+16) x all 128 cols.
// SMEM (bf16, row pad 136): B 34816 B | A0 69632 B | A1 69632 B = 174080 B.
// ===========================================================================
#define K3_SMEM (34816 + 2 * 69632)

__device__ __forceinline__ void load_tile_bf16(const float* __restrict__ src,
                                               __nv_bfloat16* __restrict__ dst,
                                               int t, int rows) {
    const float4* s4 = reinterpret_cast<const float4*>(src);
    int n4 = rows * 32;
    for (int i = t; i < n4; i += K3_THREADS) {
        int r = i >> 5, c4 = i & 31;
        float4 v = s4[i];
        __nv_bfloat162 p0 = __floats2bfloat162_rn(v.x, v.y);
        __nv_bfloat162 p1 = __floats2bfloat162_rn(v.z, v.w);
        uint2 u;
        u.x = *reinterpret_cast<uint32_t*>(&p0);
        u.y = *reinterpret_cast<uint32_t*>(&p1);
        *reinterpret_cast<uint2*>(dst + r * ROWP + c4 * 4) = u;
    }
}

__global__ void __launch_bounds__(K3_THREADS, 1) k3_main(const float* __restrict__ in,
                                                         const float* __restrict__ Wself,
                                                         float* __restrict__ out) {
    extern __shared__ __nv_bfloat16 smem[];
    __nv_bfloat16* Bs = smem;                       // [128][136]
    __nv_bfloat16* A0 = smem + 128 * ROWP;          // [256][136]
    __nv_bfloat16* A1 = A0 + TILE_R * ROWP;

    int t = threadIdx.x;
    int wid = t >> 5, lane = t & 31;
    int lr = lane >> 2, lc = lane & 3;
    int r0 = wid * 16;                              // warp row strip in tile

    load_tile_bf16(Wself, Bs, t, 128);
    load_tile_bf16(in + (size_t)blockIdx.x * TILE_R * DD, A0, t, TILE_R);
    __syncthreads();

    int it = 0;
    for (int tile = blockIdx.x; tile < N_TILES; tile += gridDim.x, it++) {
        __nv_bfloat16* cur = (it & 1) ? A1 : A0;
        __nv_bfloat16* nxt = (it & 1) ? A0 : A1;

        // Prefetch next tile into the buffer MMA'd last iteration
        int ntile = tile + gridDim.x;
        if (ntile < N_TILES)
            load_tile_bf16(in + (size_t)ntile * TILE_R * DD, nxt, t, TILE_R);

        // ---- MMA: warp strip rows [r0, r0+16) x 128 cols, K = 128 ----
        float acc[16][4];
#pragma unroll
        for (int nt = 0; nt < 16; nt++)
#pragma unroll
            for (int q = 0; q < 4; q++) acc[nt][q] = 0.f;

        const __nv_bfloat16* Arow0 = cur + (r0 + lr) * ROWP;
        const __nv_bfloat16* Arow8 = cur + (r0 + lr + 8) * ROWP;
        const __nv_bfloat16* Brow = Bs + lr * ROWP;

#pragma unroll
        for (int kk = 0; kk < 8; kk++) {
            int k0 = kk * 16 + 2 * lc;
            uint32_t a0 = *reinterpret_cast<const uint32_t*>(Arow0 + k0);
            uint32_t a1 = *reinterpret_cast<const uint32_t*>(Arow8 + k0);
            uint32_t a2 = *reinterpret_cast<const uint32_t*>(Arow0 + k0 + 8);
            uint32_t a3 = *reinterpret_cast<const uint32_t*>(Arow8 + k0 + 8);
#pragma unroll
            for (int nt = 0; nt < 16; nt++) {
                uint32_t b0 = *reinterpret_cast<const uint32_t*>(Brow + nt * 8 * ROWP + k0);
                uint32_t b1 = *reinterpret_cast<const uint32_t*>(Brow + nt * 8 * ROWP + k0 + 8);
                asm volatile(
                    "mma.sync.aligned.m16n8k16.row.col.f32.bf16.bf16.f32 "
                    "{%0,%1,%2,%3},{%4,%5,%6,%7},{%8,%9},{%0,%1,%2,%3};"
                    : "+f"(acc[nt][0]), "+f"(acc[nt][1]),
                      "+f"(acc[nt][2]), "+f"(acc[nt][3])
                    : "r"(a0), "r"(a1), "r"(a2), "r"(a3), "r"(b0), "r"(b1));
            }
        }

        // ---- Epilogue: + zm[bm,:] + zk[bk,:], direct STG.64 (32B sectors) ----
        int grow = (tile << 8) + r0 + lr;           // global row (lr part)
        int bm = grow >> 6;                          // b*64 + m (same for +8 row)
        int bk = ((grow >> 12) << 6) | (grow & 63);  // b*64 + k
        const float2* zmrow = reinterpret_cast<const float2*>(g_zm + (size_t)bm * HH);
        const float2* zkr0 = reinterpret_cast<const float2*>(g_zk + (size_t)bk * HH);
        const float2* zkr8 = reinterpret_cast<const float2*>(g_zk + (size_t)(bk + 8) * HH);
        float2* o0 = reinterpret_cast<float2*>(out + (size_t)grow * HH);
        float2* o8 = reinterpret_cast<float2*>(out + (size_t)(grow + 8) * HH);

#pragma unroll
        for (int nt = 0; nt < 16; nt++) {
            int cw = nt * 4 + lc;                    // float2 column index
            float2 zm2 = zmrow[cw];
            float2 za = zkr0[cw];
            float2 zb = zkr8[cw];
            float2 v0, v8;
            v0.x = acc[nt][0] + zm2.x + za.x;
            v0.y = acc[nt][1] + zm2.y + za.y;
            v8.x = acc[nt][2] + zm2.x + zb.x;
            v8.y = acc[nt][3] + zm2.y + zb.y;
            o0[cw] = v0;
            o8[cw] = v8;
        }
        __syncthreads();
    }
}

// ===========================================================================
extern "C" void kernel_launch(void* const* d_in, const int* in_sizes, int n_in,
                              void* d_out, int out_size) {
    const float* inputs = (const float*)d_in[0];
    const float* Wself  = (const float*)d_in[1];
    const float* Wm     = (const float*)d_in[2];
    const float* Wk     = (const float*)d_in[3];
    float* out = (float*)d_out;
    (void)in_sizes; (void)n_in; (void)out_size;

    const size_t S2 = (size_t)(128 * 129 + 64 * 129) * sizeof(float);
    cudaFuncSetAttribute(k2_bias, cudaFuncAttributeMaxDynamicSharedMemorySize, (int)S2);
    cudaFuncSetAttribute(k3_main, cudaFuncAttributeMaxDynamicSharedMemorySize, K3_SMEM);

    k1_reduce<<<2048, 128>>>(inputs);
    k2_bias<<<128, 128, S2>>>(Wm, Wk);
    k3_main<<<148, K3_THREADS, K3_SMEM>>>(inputs, Wself, out);
}